// round 1
// baseline (speedup 1.0000x reference)
#include <cuda_runtime.h>
#include <math.h>

#define B_     16
#define C_     512
#define N_     1024
#define HEADS  8
#define CH     64
#define GROUPS 32
#define CPG    16   // channels per group

// ---------------- scratch (static device globals; no allocation) ----------------
__device__ float g_xn [B_ * C_ * N_];        //  33.5 MB  group-normed x  [b,c,n]
__device__ float g_qkv[B_ * 3 * C_ * N_];    // 100.7 MB  qkv             [b,3c,n]
__device__ float g_att[B_ * C_ * N_];        //  33.5 MB  attn out        [b,c,n]

// ======================================================================
// 1) GroupNorm: one block per (batch, group); 16*1024 = 16384 elems/group
// ======================================================================
__global__ __launch_bounds__(256)
void groupnorm_kernel(const float* __restrict__ x,
                      const float* __restrict__ w,
                      const float* __restrict__ bias)
{
    const int batch = blockIdx.x >> 5;
    const int g     = blockIdx.x & 31;
    const float* xp = x    + ((size_t)batch * C_ + g * CPG) * N_;
    float*       op = g_xn + ((size_t)batch * C_ + g * CPG) * N_;
    const int NE = CPG * N_; // 16384

    float s = 0.f, s2 = 0.f;
    for (int i = threadIdx.x; i < NE; i += 256) {
        float v = xp[i];
        s += v; s2 += v * v;
    }
    __shared__ float rs[8], rs2[8];
    #pragma unroll
    for (int o = 16; o > 0; o >>= 1) {
        s  += __shfl_down_sync(0xffffffffu, s,  o);
        s2 += __shfl_down_sync(0xffffffffu, s2, o);
    }
    const int wid = threadIdx.x >> 5, lane = threadIdx.x & 31;
    if (lane == 0) { rs[wid] = s; rs2[wid] = s2; }
    __syncthreads();
    if (wid == 0) {
        s  = (lane < 8) ? rs[lane]  : 0.f;
        s2 = (lane < 8) ? rs2[lane] : 0.f;
        #pragma unroll
        for (int o = 4; o > 0; o >>= 1) {
            s  += __shfl_down_sync(0xffffffffu, s,  o);
            s2 += __shfl_down_sync(0xffffffffu, s2, o);
        }
        if (lane == 0) { rs[0] = s; rs2[0] = s2; }
    }
    __syncthreads();
    const float mean = rs[0] * (1.f / NE);
    const float var  = rs2[0] * (1.f / NE) - mean * mean;
    const float inv  = rsqrtf(var + 1e-5f);
    for (int i = threadIdx.x; i < NE; i += 256) {
        int ch = g * CPG + (i >> 10);
        op[i] = (xp[i] - mean) * inv * w[ch] + bias[ch];
    }
}

// ======================================================================
// 2) Batched SGEMM body: C[b] = A[M,K] * B[b][K,N] + bias (+ residual)
//    BM=BN=128, BK=8, 256 threads, 8x8 register tile per thread
// ======================================================================
template<int M, int N, int K, bool HAS_RES>
__device__ __forceinline__
void gemm_body(const float* __restrict__ A,
               const float* __restrict__ Bglob,
               const float* __restrict__ bias,
               const float* __restrict__ ResGlob,
               float* __restrict__ Cglob)
{
    constexpr int BM = 128, BN = 128, BK = 8;
    __shared__ float As[BK][BM];
    __shared__ float Bs[BK][BN];

    const int bN = blockIdx.x * BN;
    const int bM = blockIdx.y * BM;
    const float* B  = Bglob + (size_t)blockIdx.z * K * N;
    float*       C  = Cglob + (size_t)blockIdx.z * M * N;
    const float* R  = HAS_RES ? (ResGlob + (size_t)blockIdx.z * M * N) : nullptr;

    const int tid  = threadIdx.x;
    const int arow = tid >> 1;           // 0..127
    const int acol = (tid & 1) * 4;      // 0 or 4
    const int brow = tid >> 5;           // 0..7
    const int bcol = (tid & 31) * 4;     // 0..124

    const int ty = tid >> 4;  // 0..15  -> rows ty*8..+7
    const int tx = tid & 15;  // 0..15  -> cols tx*8..+7

    float acc[8][8];
    #pragma unroll
    for (int i = 0; i < 8; i++)
        #pragma unroll
        for (int j = 0; j < 8; j++) acc[i][j] = 0.f;

    for (int k0 = 0; k0 < K; k0 += BK) {
        float4 av = *(const float4*)(A + (size_t)(bM + arow) * K + k0 + acol);
        As[acol + 0][arow] = av.x;
        As[acol + 1][arow] = av.y;
        As[acol + 2][arow] = av.z;
        As[acol + 3][arow] = av.w;
        float4 bv = *(const float4*)(B + (size_t)(k0 + brow) * N + bN + bcol);
        *(float4*)&Bs[brow][bcol] = bv;
        __syncthreads();

        #pragma unroll
        for (int kk = 0; kk < BK; kk++) {
            float a[8], bb[8];
            *(float4*)(a)      = *(const float4*)&As[kk][ty * 8];
            *(float4*)(a + 4)  = *(const float4*)&As[kk][ty * 8 + 4];
            *(float4*)(bb)     = *(const float4*)&Bs[kk][tx * 8];
            *(float4*)(bb + 4) = *(const float4*)&Bs[kk][tx * 8 + 4];
            #pragma unroll
            for (int i = 0; i < 8; i++)
                #pragma unroll
                for (int j = 0; j < 8; j++)
                    acc[i][j] += a[i] * bb[j];
        }
        __syncthreads();
    }

    #pragma unroll
    for (int i = 0; i < 8; i++) {
        const int row = bM + ty * 8 + i;
        const float bs = bias[row];
        #pragma unroll
        for (int j4 = 0; j4 < 2; j4++) {
            const int col = bN + tx * 8 + j4 * 4;
            float4 v;
            v.x = acc[i][j4 * 4 + 0] + bs;
            v.y = acc[i][j4 * 4 + 1] + bs;
            v.z = acc[i][j4 * 4 + 2] + bs;
            v.w = acc[i][j4 * 4 + 3] + bs;
            if (HAS_RES) {
                float4 r = *(const float4*)(R + (size_t)row * N + col);
                v.x += r.x; v.y += r.y; v.z += r.z; v.w += r.w;
            }
            *(float4*)(C + (size_t)row * N + col) = v;
        }
    }
}

__global__ __launch_bounds__(256)
void qkv_gemm_kernel(const float* __restrict__ W, const float* __restrict__ bias)
{
    gemm_body<3 * C_, N_, C_, false>(W, g_xn, bias, nullptr, g_qkv);
}

__global__ __launch_bounds__(256)
void proj_gemm_kernel(const float* __restrict__ W, const float* __restrict__ bias,
                      const float* __restrict__ x, float* __restrict__ out)
{
    gemm_body<C_, N_, C_, true>(W, g_att, bias, x, out);
}

// ======================================================================
// 3) Attention: flash-style online softmax, 1 query per thread.
//    Block = 128 threads = 128 queries, per (batch, head).
//    qkv layout per batch: [3c, n]; Q rows h*64.., K rows 512+h*64..,
//    V rows 1024+h*64..
// ======================================================================
__global__ __launch_bounds__(128, 2)
void attn_kernel()
{
    const int b = blockIdx.z;
    const int h = blockIdx.y;
    const int q = blockIdx.x * 128 + threadIdx.x;

    const float* base = g_qkv + (size_t)b * (3 * C_) * N_;
    const float* Qp = base + (size_t)(h * CH) * N_;
    const float* Kp = base + (size_t)(C_ + h * CH) * N_;
    const float* Vp = base + (size_t)(2 * C_ + h * CH) * N_;

    __shared__ float Ks[CH][32];
    __shared__ float Vs[CH][32];

    float qv[CH];
    #pragma unroll
    for (int d = 0; d < CH; d++) qv[d] = Qp[d * N_ + q] * 0.125f;  // 64^-0.5

    float acc[CH];
    #pragma unroll
    for (int d = 0; d < CH; d++) acc[d] = 0.f;
    float m = -INFINITY, l = 0.f;

    for (int j0 = 0; j0 < N_; j0 += 32) {
        // cooperative load of K/V tile [64 dims x 32 keys]
        for (int t = threadIdx.x; t < CH * 32; t += 128) {
            const int j = t & 31, d = t >> 5;
            Ks[d][j] = Kp[d * N_ + j0 + j];
            Vs[d][j] = Vp[d * N_ + j0 + j];
        }
        __syncthreads();

        float s[32];
        #pragma unroll
        for (int j = 0; j < 32; j++) s[j] = 0.f;

        #pragma unroll
        for (int d = 0; d < CH; d++) {
            const float4* kr = (const float4*)Ks[d];
            const float qd = qv[d];
            #pragma unroll
            for (int j4 = 0; j4 < 8; j4++) {
                float4 kk = kr[j4];            // broadcast read
                s[j4 * 4 + 0] += qd * kk.x;
                s[j4 * 4 + 1] += qd * kk.y;
                s[j4 * 4 + 2] += qd * kk.z;
                s[j4 * 4 + 3] += qd * kk.w;
            }
        }

        float tm = m;
        #pragma unroll
        for (int j = 0; j < 32; j++) tm = fmaxf(tm, s[j]);
        const float corr = __expf(m - tm);
        m = tm;
        l *= corr;
        #pragma unroll
        for (int d = 0; d < CH; d++) acc[d] *= corr;
        #pragma unroll
        for (int j = 0; j < 32; j++) {
            s[j] = __expf(s[j] - m);
            l += s[j];
        }
        #pragma unroll
        for (int d = 0; d < CH; d++) {
            const float4* vr = (const float4*)Vs[d];
            float a = acc[d];
            #pragma unroll
            for (int j4 = 0; j4 < 8; j4++) {
                float4 vv = vr[j4];            // broadcast read
                a += s[j4 * 4 + 0] * vv.x;
                a += s[j4 * 4 + 1] * vv.y;
                a += s[j4 * 4 + 2] * vv.z;
                a += s[j4 * 4 + 3] * vv.w;
            }
            acc[d] = a;
        }
        __syncthreads();
    }

    const float inv = 1.f / l;
    float* op = g_att + (size_t)b * C_ * N_ + (size_t)(h * CH) * N_;
    #pragma unroll
    for (int d = 0; d < CH; d++) op[d * N_ + q] = acc[d] * inv;
}

// ======================================================================
// launch
// ======================================================================
extern "C" void kernel_launch(void* const* d_in, const int* in_sizes, int n_in,
                              void* d_out, int out_size)
{
    const float* x      = (const float*)d_in[0];
    const float* norm_w = (const float*)d_in[1];
    const float* norm_b = (const float*)d_in[2];
    const float* qkv_w  = (const float*)d_in[3];
    const float* qkv_b  = (const float*)d_in[4];
    const float* proj_w = (const float*)d_in[5];
    const float* proj_b = (const float*)d_in[6];
    float* out = (float*)d_out;

    // 1) GroupNorm
    groupnorm_kernel<<<B_ * GROUPS, 256>>>(x, norm_w, norm_b);

    // 2) QKV GEMM: [1536,512] x [b][512,1024]
    {
        dim3 grid(N_ / 128, (3 * C_) / 128, B_);
        qkv_gemm_kernel<<<grid, 256>>>(qkv_w, qkv_b);
    }

    // 3) Attention
    {
        dim3 grid(N_ / 128, HEADS, B_);
        attn_kernel<<<grid, 128>>>();
    }

    // 4) Proj GEMM + bias + residual -> d_out
    {
        dim3 grid(N_ / 128, C_ / 128, B_);
        proj_gemm_kernel<<<grid, 256>>>(proj_w, proj_b, x, out);
    }
}

// round 2
// speedup vs baseline: 1.0057x; 1.0057x over previous
#include <cuda_runtime.h>
#include <math.h>

#define B_     16
#define C_     512
#define N_     1024
#define HEADS  8
#define CH     64
#define GROUPS 32
#define CPG    16   // channels per group

// ---------------- scratch (static device globals; no allocation) ----------------
__device__ float g_xn [B_ * C_ * N_];        //  33.5 MB  group-normed x  [b,c,n]
__device__ float g_qkv[B_ * 3 * C_ * N_];    // 100.7 MB  qkv             [b,3c,n]
__device__ float g_att[B_ * C_ * N_];        //  33.5 MB  attn out        [b,c,n]

// ======================================================================
// 1) GroupNorm: one block per (batch, group); 16*1024 = 16384 elems/group
// ======================================================================
__global__ __launch_bounds__(256)
void groupnorm_kernel(const float* __restrict__ x,
                      const float* __restrict__ w,
                      const float* __restrict__ bias)
{
    const int batch = blockIdx.x >> 5;
    const int g     = blockIdx.x & 31;
    const float* xp = x    + ((size_t)batch * C_ + g * CPG) * N_;
    float*       op = g_xn + ((size_t)batch * C_ + g * CPG) * N_;
    const int NE = CPG * N_; // 16384

    float s = 0.f, s2 = 0.f;
    for (int i = threadIdx.x; i < NE; i += 256) {
        float v = xp[i];
        s += v; s2 += v * v;
    }
    __shared__ float rs[8], rs2[8];
    #pragma unroll
    for (int o = 16; o > 0; o >>= 1) {
        s  += __shfl_down_sync(0xffffffffu, s,  o);
        s2 += __shfl_down_sync(0xffffffffu, s2, o);
    }
    const int wid = threadIdx.x >> 5, lane = threadIdx.x & 31;
    if (lane == 0) { rs[wid] = s; rs2[wid] = s2; }
    __syncthreads();
    if (wid == 0) {
        s  = (lane < 8) ? rs[lane]  : 0.f;
        s2 = (lane < 8) ? rs2[lane] : 0.f;
        #pragma unroll
        for (int o = 4; o > 0; o >>= 1) {
            s  += __shfl_down_sync(0xffffffffu, s,  o);
            s2 += __shfl_down_sync(0xffffffffu, s2, o);
        }
        if (lane == 0) { rs[0] = s; rs2[0] = s2; }
    }
    __syncthreads();
    const float mean = rs[0] * (1.f / NE);
    const float var  = rs2[0] * (1.f / NE) - mean * mean;
    const float inv  = rsqrtf(var + 1e-5f);
    for (int i = threadIdx.x; i < NE; i += 256) {
        int ch = g * CPG + (i >> 10);
        op[i] = (xp[i] - mean) * inv * w[ch] + bias[ch];
    }
}

// ======================================================================
// 2) Batched SGEMM body: C[b] = A[M,K] * B[b][K,N] + bias (+ residual)
//    BM=BN=128, BK=8, 256 threads, 8x8 register tile per thread
// ======================================================================
template<int M, int N, int K, bool HAS_RES>
__device__ __forceinline__
void gemm_body(const float* __restrict__ A,
               const float* __restrict__ Bglob,
               const float* __restrict__ bias,
               const float* __restrict__ ResGlob,
               float* __restrict__ Cglob)
{
    constexpr int BM = 128, BN = 128, BK = 8;
    __shared__ float As[BK][BM];
    __shared__ float Bs[BK][BN];

    const int bN = blockIdx.x * BN;
    const int bM = blockIdx.y * BM;
    const float* B  = Bglob + (size_t)blockIdx.z * K * N;
    float*       C  = Cglob + (size_t)blockIdx.z * M * N;
    const float* R  = HAS_RES ? (ResGlob + (size_t)blockIdx.z * M * N) : nullptr;

    const int tid  = threadIdx.x;
    const int arow = tid >> 1;           // 0..127
    const int acol = (tid & 1) * 4;      // 0 or 4
    const int brow = tid >> 5;           // 0..7
    const int bcol = (tid & 31) * 4;     // 0..124

    const int ty = tid >> 4;  // 0..15  -> rows ty*8..+7
    const int tx = tid & 15;  // 0..15  -> cols tx*8..+7

    float acc[8][8];
    #pragma unroll
    for (int i = 0; i < 8; i++)
        #pragma unroll
        for (int j = 0; j < 8; j++) acc[i][j] = 0.f;

    for (int k0 = 0; k0 < K; k0 += BK) {
        float4 av = *(const float4*)(A + (size_t)(bM + arow) * K + k0 + acol);
        As[acol + 0][arow] = av.x;
        As[acol + 1][arow] = av.y;
        As[acol + 2][arow] = av.z;
        As[acol + 3][arow] = av.w;
        float4 bv = *(const float4*)(B + (size_t)(k0 + brow) * N + bN + bcol);
        *(float4*)&Bs[brow][bcol] = bv;
        __syncthreads();

        #pragma unroll
        for (int kk = 0; kk < BK; kk++) {
            float a[8], bb[8];
            *(float4*)(a)      = *(const float4*)&As[kk][ty * 8];
            *(float4*)(a + 4)  = *(const float4*)&As[kk][ty * 8 + 4];
            *(float4*)(bb)     = *(const float4*)&Bs[kk][tx * 8];
            *(float4*)(bb + 4) = *(const float4*)&Bs[kk][tx * 8 + 4];
            #pragma unroll
            for (int i = 0; i < 8; i++)
                #pragma unroll
                for (int j = 0; j < 8; j++)
                    acc[i][j] += a[i] * bb[j];
        }
        __syncthreads();
    }

    #pragma unroll
    for (int i = 0; i < 8; i++) {
        const int row = bM + ty * 8 + i;
        const float bs = bias[row];
        #pragma unroll
        for (int j4 = 0; j4 < 2; j4++) {
            const int col = bN + tx * 8 + j4 * 4;
            float4 v;
            v.x = acc[i][j4 * 4 + 0] + bs;
            v.y = acc[i][j4 * 4 + 1] + bs;
            v.z = acc[i][j4 * 4 + 2] + bs;
            v.w = acc[i][j4 * 4 + 3] + bs;
            if (HAS_RES) {
                float4 r = *(const float4*)(R + (size_t)row * N + col);
                v.x += r.x; v.y += r.y; v.z += r.z; v.w += r.w;
            }
            *(float4*)(C + (size_t)row * N + col) = v;
        }
    }
}

__global__ __launch_bounds__(256)
void qkv_gemm_kernel(const float* __restrict__ W, const float* __restrict__ bias)
{
    gemm_body<3 * C_, N_, C_, false>(W, g_xn, bias, nullptr, g_qkv);
}

__global__ __launch_bounds__(256)
void proj_gemm_kernel(const float* __restrict__ W, const float* __restrict__ bias,
                      const float* __restrict__ x, float* __restrict__ out)
{
    gemm_body<C_, N_, C_, true>(W, g_att, bias, x, out);
}

// ======================================================================
// 3) Attention: flash-style online softmax, 1 query per thread.
//    Block = 128 threads = 128 queries, per (batch, head).
//    qkv layout per batch: [3c, n]; Q rows h*64.., K rows 512+h*64..,
//    V rows 1024+h*64..
// ======================================================================
__global__ __launch_bounds__(128, 2)
void attn_kernel()
{
    const int b = blockIdx.z;
    const int h = blockIdx.y;
    const int q = blockIdx.x * 128 + threadIdx.x;

    const float* base = g_qkv + (size_t)b * (3 * C_) * N_;
    const float* Qp = base + (size_t)(h * CH) * N_;
    const float* Kp = base + (size_t)(C_ + h * CH) * N_;
    const float* Vp = base + (size_t)(2 * C_ + h * CH) * N_;

    __shared__ float Ks[CH][32];
    __shared__ float Vs[CH][32];

    float qv[CH];
    #pragma unroll
    for (int d = 0; d < CH; d++) qv[d] = Qp[d * N_ + q] * 0.125f;  // 64^-0.5

    float acc[CH];
    #pragma unroll
    for (int d = 0; d < CH; d++) acc[d] = 0.f;
    float m = -INFINITY, l = 0.f;

    for (int j0 = 0; j0 < N_; j0 += 32) {
        // cooperative load of K/V tile [64 dims x 32 keys]
        for (int t = threadIdx.x; t < CH * 32; t += 128) {
            const int j = t & 31, d = t >> 5;
            Ks[d][j] = Kp[d * N_ + j0 + j];
            Vs[d][j] = Vp[d * N_ + j0 + j];
        }
        __syncthreads();

        float s[32];
        #pragma unroll
        for (int j = 0; j < 32; j++) s[j] = 0.f;

        #pragma unroll
        for (int d = 0; d < CH; d++) {
            const float4* kr = (const float4*)Ks[d];
            const float qd = qv[d];
            #pragma unroll
            for (int j4 = 0; j4 < 8; j4++) {
                float4 kk = kr[j4];            // broadcast read
                s[j4 * 4 + 0] += qd * kk.x;
                s[j4 * 4 + 1] += qd * kk.y;
                s[j4 * 4 + 2] += qd * kk.z;
                s[j4 * 4 + 3] += qd * kk.w;
            }
        }

        float tm = m;
        #pragma unroll
        for (int j = 0; j < 32; j++) tm = fmaxf(tm, s[j]);
        const float corr = __expf(m - tm);
        m = tm;
        l *= corr;
        #pragma unroll
        for (int d = 0; d < CH; d++) acc[d] *= corr;
        #pragma unroll
        for (int j = 0; j < 32; j++) {
            s[j] = __expf(s[j] - m);
            l += s[j];
        }
        #pragma unroll
        for (int d = 0; d < CH; d++) {
            const float4* vr = (const float4*)Vs[d];
            float a = acc[d];
            #pragma unroll
            for (int j4 = 0; j4 < 8; j4++) {
                float4 vv = vr[j4];            // broadcast read
                a += s[j4 * 4 + 0] * vv.x;
                a += s[j4 * 4 + 1] * vv.y;
                a += s[j4 * 4 + 2] * vv.z;
                a += s[j4 * 4 + 3] * vv.w;
            }
            acc[d] = a;
        }
        __syncthreads();
    }

    const float inv = 1.f / l;
    float* op = g_att + (size_t)b * C_ * N_ + (size_t)(h * CH) * N_;
    #pragma unroll
    for (int d = 0; d < CH; d++) op[d * N_ + q] = acc[d] * inv;
}

// ======================================================================
// launch
// ======================================================================
extern "C" void kernel_launch(void* const* d_in, const int* in_sizes, int n_in,
                              void* d_out, int out_size)
{
    const float* x      = (const float*)d_in[0];
    const float* norm_w = (const float*)d_in[1];
    const float* norm_b = (const float*)d_in[2];
    const float* qkv_w  = (const float*)d_in[3];
    const float* qkv_b  = (const float*)d_in[4];
    const float* proj_w = (const float*)d_in[5];
    const float* proj_b = (const float*)d_in[6];
    float* out = (float*)d_out;

    // 1) GroupNorm
    groupnorm_kernel<<<B_ * GROUPS, 256>>>(x, norm_w, norm_b);

    // 2) QKV GEMM: [1536,512] x [b][512,1024]
    {
        dim3 grid(N_ / 128, (3 * C_) / 128, B_);
        qkv_gemm_kernel<<<grid, 256>>>(qkv_w, qkv_b);
    }

    // 3) Attention
    {
        dim3 grid(N_ / 128, HEADS, B_);
        attn_kernel<<<grid, 128>>>();
    }

    // 4) Proj GEMM + bias + residual -> d_out
    {
        dim3 grid(N_ / 128, C_ / 128, B_);
        proj_gemm_kernel<<<grid, 256>>>(proj_w, proj_b, x, out);
    }
}